// round 2
// baseline (speedup 1.0000x reference)
#include <cuda_runtime.h>
#include <cuda_bf16.h>

// Problem constants
#define BN   32
#define CI   128
#define CO   256
#define HH   56
#define WW   56
#define EE   4
#define RR   16
#define HW   (HH*WW)        // 3136
#define KVOL 9
#define CIK  (CI*KVOL)      // 1152
#define PERB (CO*CI*KVOL)   // 294912 weights per sample
#define PERB4 (PERB/4)      // 73728 float4 per sample

// Scratch (static device allocations are allowed; cudaMalloc is not)
__device__ float g_gap[BN*CI];
__device__ float g_rout[BN*EE];
__device__ float g_kern[BN*CO*CI*KVOL];   // 9.4M floats = 37.7 MB mixed kernels

// ---------------------------------------------------------------------------
// Kernel 1: global average pool  gap[b][ci] = mean over HW
// grid = BN*CI blocks, 256 threads
// ---------------------------------------------------------------------------
__global__ void gap_kernel(const float* __restrict__ x) {
    int bc = blockIdx.x;                    // b*CI + ci
    const float* p = x + (size_t)bc * HW;
    float s = 0.f;
    for (int i = threadIdx.x; i < HW; i += 256) s += p[i];
    __shared__ float red[256];
    red[threadIdx.x] = s;
    __syncthreads();
    for (int o = 128; o > 0; o >>= 1) {
        if (threadIdx.x < o) red[threadIdx.x] += red[threadIdx.x + o];
        __syncthreads();
    }
    if (threadIdx.x == 0) g_gap[bc] = red[0] * (1.0f / (float)HW);
}

// ---------------------------------------------------------------------------
// Kernel 2: router MLP + softmax(logits/30). 1 block, 32 threads (1 per b)
// ---------------------------------------------------------------------------
__global__ void rout_kernel(const float* __restrict__ w1, const float* __restrict__ b1,
                            const float* __restrict__ w2, const float* __restrict__ b2) {
    int b = threadIdx.x;
    if (b >= BN) return;
    float h[RR];
    #pragma unroll
    for (int j = 0; j < RR; ++j) {
        float s = b1[j];
        for (int i = 0; i < CI; ++i) s += w1[j*CI + i] * g_gap[b*CI + i];
        h[j] = fmaxf(s, 0.f);
    }
    float lg[EE];
    float mx = -1e30f;
    #pragma unroll
    for (int e = 0; e < EE; ++e) {
        float s = b2[e];
        #pragma unroll
        for (int j = 0; j < RR; ++j) s += w2[e*RR + j] * h[j];
        lg[e] = s * (1.0f / 30.0f);
        mx = fmaxf(mx, lg[e]);
    }
    float den = 0.f;
    #pragma unroll
    for (int e = 0; e < EE; ++e) { lg[e] = __expf(lg[e] - mx); den += lg[e]; }
    float inv = 1.0f / den;
    #pragma unroll
    for (int e = 0; e < EE; ++e) g_rout[b*EE + e] = lg[e] * inv;
}

// ---------------------------------------------------------------------------
// Kernel 3: mix expert banks -> g_kern[b] = sum_e rout[b][e] * convs[e]
// float4 vectorized grid-stride
// ---------------------------------------------------------------------------
__global__ void mix_kernel(const float* __restrict__ convs) {
    int idx = blockIdx.x * blockDim.x + threadIdx.x;
    const int total = BN * PERB4;
    if (idx >= total) return;
    int b = idx / PERB4;
    int j = idx - b * PERB4;
    float r0 = g_rout[b*EE + 0];
    float r1 = g_rout[b*EE + 1];
    float r2 = g_rout[b*EE + 2];
    float r3 = g_rout[b*EE + 3];
    const float4* c4 = (const float4*)convs;
    float4 a = c4[0*PERB4 + j];
    float4 bb = c4[1*PERB4 + j];
    float4 c = c4[2*PERB4 + j];
    float4 d = c4[3*PERB4 + j];
    float4 o;
    o.x = r0*a.x + r1*bb.x + r2*c.x + r3*d.x;
    o.y = r0*a.y + r1*bb.y + r2*c.y + r3*d.y;
    o.z = r0*a.z + r1*bb.z + r2*c.z + r3*d.z;
    o.w = r0*a.w + r1*bb.w + r2*c.w + r3*d.w;
    ((float4*)g_kern)[idx] = o;
}

// ---------------------------------------------------------------------------
// Kernel 4: direct conv, 3x3, pad 1, per-sample mixed kernels.
// Block: (oh tile of 4 rows) x (64 couts) x (b)
// 256 threads: t%32 = pixel group (32 groups of 7 px over 4x56 tile),
//              t/32 = cout group (8 groups of 8 couts)
// Thread computes 8 couts x 7 pixels = 56 accumulators.
// ---------------------------------------------------------------------------
#define CIC   4
#define NCHNK (CI/CIC)    // 32
#define ROWS  4
#define COT   64
#define TCO   8
#define TPX   7

__global__ void __launch_bounds__(256)
conv_kernel(const float* __restrict__ x, float* __restrict__ out) {
    __shared__ float xs[CIC][ROWS+2][58];       // halo tile, 5.6 KB
    __shared__ float ws[COT*CIC*KVOL];          // [co][ci][k], 9.2 KB

    const int b       = blockIdx.z;
    const int co_base = blockIdx.y * COT;
    const int oh_base = blockIdx.x * ROWS;
    const int t  = threadIdx.x;
    const int g  = t & 31;                      // pixel group
    const int cg = t >> 5;                      // cout group (warp-uniform)
    const int r  = g >> 3;                      // row within tile
    const int c0 = (g & 7) * TPX;               // col base

    float acc[TCO][TPX];
    #pragma unroll
    for (int u = 0; u < TCO; ++u)
        #pragma unroll
        for (int j = 0; j < TPX; ++j) acc[u][j] = 0.f;

    const float* xb = x + (size_t)b * CI * HW;
    const float* kb = g_kern + ((size_t)b * CO + co_base) * CIK;

    for (int cc = 0; cc < NCHNK; ++cc) {
        const int ci0 = cc * CIC;
        // stage x halo tile: CIC * 6 * 58 = 1392 floats
        for (int m = t; m < CIC*6*58; m += 256) {
            int ci  = m / (6*58);
            int rem = m - ci*(6*58);
            int row = rem / 58;
            int col = rem - row*58;
            int gh = oh_base + row - 1;
            int gw = col - 1;
            float v = 0.f;
            if ((unsigned)gh < HH && (unsigned)gw < WW)
                v = xb[(ci0 + ci)*HW + gh*WW + gw];
            xs[ci][row][col] = v;
        }
        // stage mixed weights: 64co * 4ci * 9 = 2304 floats
        for (int m = t; m < COT*CIC*KVOL; m += 256) {
            int co  = m / (CIC*KVOL);
            int rem = m - co*(CIC*KVOL);        // ci*9 + k, contiguous in gmem
            ws[m] = kb[co*CIK + ci0*KVOL + rem];
        }
        __syncthreads();

        const float* wt = ws + cg * TCO * (CIC*KVOL);
        #pragma unroll
        for (int ci = 0; ci < CIC; ++ci) {
            #pragma unroll
            for (int kh = 0; kh < 3; ++kh) {
                float xv[TPX+2];
                #pragma unroll
                for (int j = 0; j < TPX+2; ++j) xv[j] = xs[ci][r+kh][c0+j];
                #pragma unroll
                for (int kw = 0; kw < 3; ++kw) {
                    float wv[TCO];
                    #pragma unroll
                    for (int u = 0; u < TCO; ++u)
                        wv[u] = wt[u*(CIC*KVOL) + ci*KVOL + kh*3 + kw];
                    #pragma unroll
                    for (int u = 0; u < TCO; ++u)
                        #pragma unroll
                        for (int j = 0; j < TPX; ++j)
                            acc[u][j] = fmaf(wv[u], xv[kw+j], acc[u][j]);
                }
            }
        }
        __syncthreads();
    }

    // write 8x7 outputs
    #pragma unroll
    for (int u = 0; u < TCO; ++u) {
        int co = co_base + cg*TCO + u;
        float* op = out + (((size_t)b*CO + co)*HH + oh_base + r)*WW + c0;
        #pragma unroll
        for (int j = 0; j < TPX; ++j) op[j] = acc[u][j];
    }
}

// ---------------------------------------------------------------------------
extern "C" void kernel_launch(void* const* d_in, const int* in_sizes, int n_in,
                              void* d_out, int out_size) {
    const float* x     = (const float*)d_in[0];
    const float* convs = (const float*)d_in[1];
    const float* w1    = (const float*)d_in[2];
    const float* b1    = (const float*)d_in[3];
    const float* w2    = (const float*)d_in[4];
    const float* b2    = (const float*)d_in[5];
    float* out = (float*)d_out;

    gap_kernel<<<BN*CI, 256>>>(x);
    rout_kernel<<<1, 32>>>(w1, b1, w2, b2);
    {
        const int total = BN * PERB4;
        mix_kernel<<<(total + 255)/256, 256>>>(convs);
    }
    {
        dim3 grid(HH/ROWS, CO/COT, BN);   // 14 x 4 x 32
        conv_kernel<<<grid, 256>>>(x, out);
    }
    (void)in_sizes; (void)n_in; (void)out_size;
}